// round 8
// baseline (speedup 1.0000x reference)
#include <cuda_runtime.h>
#include <cstdint>

#define K_TOP    30
#define EMB_DIM  128
#define ROW_B    (EMB_DIM * 4)     // 512 bytes per row
#define NT       128               // 4 warps per block

// Map float -> uint32 whose unsigned order matches float order (ascending).
__device__ __forceinline__ unsigned int float_to_sortable(float f) {
    unsigned int b = __float_as_uint(f);
    return (b & 0x80000000u) ? ~b : (b | 0x80000000u);
}

__device__ __forceinline__ unsigned long long shflx64(unsigned long long x, int m) {
    unsigned lo = (unsigned)x, hi = (unsigned)(x >> 32);
    lo = __shfl_xor_sync(0xffffffffu, lo, m);
    hi = __shfl_xor_sync(0xffffffffu, hi, m);
    return ((unsigned long long)hi << 32) | lo;
}

__device__ __forceinline__ unsigned long long cmpx(unsigned long long a,
                                                   unsigned long long b,
                                                   bool keep_max) {
    unsigned long long mx = a > b ? a : b;
    unsigned long long mn = a > b ? b : a;
    return keep_max ? mx : mn;
}

// 5-stage descending bitonic merge (32-wide) of a bitonic sequence.
__device__ __forceinline__ unsigned long long warp_merge_desc(unsigned long long key,
                                                              int lane) {
    #pragma unroll
    for (int j = 16; j >= 1; j >>= 1) {
        bool lower = (lane & j) == 0;
        unsigned long long other = shflx64(key, j);
        key = cmpx(key, other, lower);
    }
    return key;
}

// ---- async-proxy helpers ----
__device__ __forceinline__ uint32_t smem_u32(const void* p) {
    uint32_t a;
    asm("{ .reg .u64 t; cvta.to.shared.u64 t, %1; cvt.u32.u64 %0, t; }"
        : "=r"(a) : "l"(p));
    return a;
}
__device__ __forceinline__ void mbar_init(uint32_t mb, uint32_t cnt) {
    asm volatile("mbarrier.init.shared.b64 [%0], %1;" :: "r"(mb), "r"(cnt) : "memory");
}
__device__ __forceinline__ void mbar_expect_tx(uint32_t mb, uint32_t bytes) {
    asm volatile("mbarrier.arrive.expect_tx.shared.b64 _, [%0], %1;"
                 :: "r"(mb), "r"(bytes) : "memory");
}
__device__ __forceinline__ void mbar_wait_parity0(uint32_t mb) {
    asm volatile(
        "{\n\t"
        ".reg .pred P;\n\t"
        "WAIT_%=:\n\t"
        "mbarrier.try_wait.parity.acquire.cta.shared::cta.b64 P, [%0], 0, 0x989680;\n\t"
        "@P bra.uni DONE_%=;\n\t"
        "bra.uni WAIT_%=;\n\t"
        "DONE_%=:\n\t"
        "}" :: "r"(mb) : "memory");
}
__device__ __forceinline__ void bulk_g2s(uint32_t dst_smem, const void* src,
                                         uint32_t bytes, uint32_t mb) {
    asm volatile(
        "cp.async.bulk.shared::cta.global.mbarrier::complete_tx::bytes "
        "[%0], [%1], %2, [%3];"
        :: "r"(dst_smem), "l"(src), "r"(bytes), "r"(mb) : "memory");
}
__device__ __forceinline__ void bulk_s2g(void* dst, uint32_t src_smem, uint32_t bytes) {
    asm volatile("cp.async.bulk.global.shared::cta.bulk_group [%0], [%1], %2;"
                 :: "l"(dst), "r"(src_smem), "r"(bytes) : "memory");
}
__device__ __forceinline__ void bulk_commit_wait() {
    asm volatile("cp.async.bulk.commit_group;" ::: "memory");
    asm volatile("cp.async.bulk.wait_group 0;" ::: "memory");
}
__device__ __forceinline__ void fence_async_shared() {
    asm volatile("fence.proxy.async.shared::cta;" ::: "memory");
}

__global__ void __launch_bounds__(NT)
sortpool_kernel(const float* __restrict__ emb,
                const int*   __restrict__ sizes,
                float*       __restrict__ out,
                int G) {
    const int g    = blockIdx.x;
    const int tid  = threadIdx.x;
    const int lane = tid & 31;
    const int wid  = tid >> 5;

    // stage overlays the sort-run buffer (sort runs are dead before gather).
    __shared__ __align__(128) unsigned char buf[K_TOP * ROW_B];   // 15360 B
    __shared__ __align__(8)  unsigned long long mbar_storage;
    __shared__ int wsum[NT / 32];
    __shared__ int sh_off;
    __shared__ int tops[32];

    unsigned long long* s = (unsigned long long*)buf;   // 128 slots during sort

    // ---- offset = prefix sum of sizes[0..g-1], int4-vectorized (L2-resident) ----
    int acc = 0;
    {
        const int4* s4 = (const int4*)sizes;
        const int nfull = g >> 2;
        for (int j = tid; j < nfull; j += NT) {
            int4 v = s4[j];
            acc += v.x + v.y + v.z + v.w;
        }
        if (tid < (g & 3)) acc += sizes[(nfull << 2) + tid];
    }
    #pragma unroll
    for (int m = 16; m; m >>= 1) acc += __shfl_xor_sync(0xffffffffu, acc, m);
    if (lane == 0) wsum[wid] = acc;
    __syncthreads();
    if (tid == 0) {
        int o = 0;
        #pragma unroll
        for (int w = 0; w < NT / 32; w++) o += wsum[w];
        sh_off = o;
        mbar_init(smem_u32(&mbar_storage), 1);
    }
    __syncthreads();
    const int offset = sh_off;
    const int size   = sizes[g];
    const int nw64   = (size + 63) >> 6;   // warps holding data (64 elems each)

    // Composite keys: (sortable(val) << 32) | ~elem_idx. Descending composite
    // order == descending value, ascending index on ties. Lane holds elements
    // i0 = wid*64+lane (key0) and i1 = wid*64+32+lane (key1).
    const int i0 = (wid << 6) + lane;
    const int i1 = i0 + 32;
    unsigned long long key0 = (unsigned long long)(unsigned int)(~(unsigned int)i0);
    unsigned long long key1 = (unsigned long long)(unsigned int)(~(unsigned int)i1);

    if (wid < nw64) {
        if (i0 < size) {
            float v = __ldg(&emb[(size_t)(offset + i0) * EMB_DIM + (EMB_DIM - 1)]);
            key0 |= (unsigned long long)float_to_sortable(v) << 32;
        }
        if (i1 < size) {
            float v = __ldg(&emb[(size_t)(offset + i1) * EMB_DIM + (EMB_DIM - 1)]);
            key1 |= (unsigned long long)float_to_sortable(v) << 32;
        }

        // ---- 64-element bitonic sort (descending), 2 keys per lane ----
        #pragma unroll
        for (int k = 2; k <= 16; k <<= 1) {
            const bool dir = ((lane & k) == 0);
            #pragma unroll
            for (int j = k >> 1; j >= 1; j >>= 1) {
                bool lower = (lane & j) == 0;
                key0 = cmpx(key0, shflx64(key0, j), lower == dir);
                key1 = cmpx(key1, shflx64(key1, j), lower == dir);
            }
        }
        // k = 32: key0 half descending, key1 half ascending.
        #pragma unroll
        for (int j = 16; j >= 1; j >>= 1) {
            bool lower = (lane & j) == 0;
            key0 = cmpx(key0, shflx64(key0, j), lower);
            key1 = cmpx(key1, shflx64(key1, j), !lower);
        }
        // k = 64: intra-thread compare keeps the top half, then 5-stage clean.
        {
            unsigned long long mx = key0 > key1 ? key0 : key1;
            key0 = warp_merge_desc(mx, lane);
        }
        s[(wid << 5) + lane] = key0;   // warp's top-32 of its 64, descending
    }
    __syncthreads();

    // ---- top-32 merge tree over nw64 sorted runs ----
    for (int step = 1; step < nw64; step <<= 1) {
        bool winner = ((wid & (2 * step - 1)) == 0) && (wid + step < nw64);
        if (winner) {
            unsigned long long other = s[((wid + step) << 5) + (31 - lane)];
            key0 = key0 > other ? key0 : other;
            key0 = warp_merge_desc(key0, lane);
            s[(wid << 5) + lane] = key0;
        }
        __syncthreads();
    }

    // ---- warp 0 lane r holds rank-r key; publish indices ----
    const int kmax = min(K_TOP, size);
    if (wid == 0) {
        int lidx = (int)(~(unsigned int)(key0 & 0xFFFFFFFFull));
        tops[lane] = lidx;
        if (lane < K_TOP) {
            float idxval = (lane < kmax) ? (float)(offset + lidx) : -1.0f;
            out[(size_t)G * K_TOP * EMB_DIM + (size_t)g * K_TOP + lane] = idxval;
        }
    }
    // zero pad rows (only when kmax < 30; never for this dataset, kept general)
    if (kmax < K_TOP) {
        float* pad = (float*)(buf + kmax * ROW_B);
        const int n = (K_TOP - kmax) * EMB_DIM;
        for (int i = tid; i < n; i += NT) pad[i] = 0.0f;
    }
    __syncthreads();   // tops + pad zeros + mbar init visible block-wide

    // ---- async bulk gather: 30 x 512B rows, all in flight, then async stores ----
    if (wid == 0) {
        const uint32_t mb = smem_u32(&mbar_storage);
        const uint32_t st = smem_u32(buf);
        if (lane == 0) mbar_expect_tx(mb, (uint32_t)kmax * ROW_B);
        __syncwarp();
        if (lane < kmax) {
            const char* src = (const char*)emb + (size_t)(offset + tops[lane]) * ROW_B;
            bulk_g2s(st + lane * ROW_B, src, ROW_B, mb);
        }
        mbar_wait_parity0(mb);
        fence_async_shared();          // order generic pad-zero writes for async reads
        if (lane < K_TOP) {
            char* dst = (char*)out + ((size_t)g * K_TOP + lane) * ROW_B;
            bulk_s2g(dst, st + lane * ROW_B, ROW_B);
            bulk_commit_wait();
        }
    }
}

extern "C" void kernel_launch(void* const* d_in, const int* in_sizes, int n_in,
                              void* d_out, int out_size) {
    const float* emb   = (const float*)d_in[0];
    const int*   sizes = (const int*)d_in[1];
    const int G = in_sizes[1];
    sortpool_kernel<<<G, NT>>>(emb, sizes, (float*)d_out, G);
}

// round 9
// speedup vs baseline: 1.0331x; 1.0331x over previous
#include <cuda_runtime.h>
#include <cstdint>

#define K_TOP    30
#define EMB_DIM  128
#define NT       128   // 4 warps per block

// Map float -> uint32 whose unsigned order matches float order (ascending).
__device__ __forceinline__ unsigned int float_to_sortable(float f) {
    unsigned int b = __float_as_uint(f);
    return (b & 0x80000000u) ? ~b : (b | 0x80000000u);
}

__device__ __forceinline__ unsigned long long shflx64(unsigned long long x, int m) {
    unsigned lo = (unsigned)x, hi = (unsigned)(x >> 32);
    lo = __shfl_xor_sync(0xffffffffu, lo, m);
    hi = __shfl_xor_sync(0xffffffffu, hi, m);
    return ((unsigned long long)hi << 32) | lo;
}

__device__ __forceinline__ unsigned long long cmpx(unsigned long long a,
                                                   unsigned long long b,
                                                   bool keep_max) {
    unsigned long long mx = a > b ? a : b;
    unsigned long long mn = a > b ? b : a;
    return keep_max ? mx : mn;
}

__device__ __forceinline__ unsigned cmpx32(unsigned a, unsigned b, bool keep_max) {
    unsigned mx = a > b ? a : b;
    unsigned mn = a > b ? b : a;
    return keep_max ? mx : mn;
}

// 5-stage descending bitonic merge (32-wide) of a bitonic sequence.
__device__ __forceinline__ unsigned long long warp_merge_desc(unsigned long long key,
                                                              int lane) {
    #pragma unroll
    for (int j = 16; j >= 1; j >>= 1) {
        bool lower = (lane & j) == 0;
        unsigned long long other = shflx64(key, j);
        key = cmpx(key, other, lower);
    }
    return key;
}

__global__ void __launch_bounds__(NT)
sortpool_kernel(const float* __restrict__ emb,
                const int*   __restrict__ sizes,
                float*       __restrict__ out,
                int G) {
    const int g    = blockIdx.x;
    const int tid  = threadIdx.x;
    const int lane = tid & 31;
    const int wid  = tid >> 5;

    __shared__ unsigned long long s[NT];      // one 32-slot run per warp
    __shared__ int wsum[NT / 32];
    __shared__ int sh_off;
    __shared__ int sidx[32];                  // winner node indices, addr-ascending
    __shared__ int srank[32];                 // rank (output row) of each winner

    // ---- offset = prefix sum of sizes[0..g-1], int4-vectorized (L2-resident) ----
    int acc = 0;
    {
        const int4* s4 = (const int4*)sizes;
        const int nfull = g >> 2;
        for (int j = tid; j < nfull; j += NT) {
            int4 v = s4[j];
            acc += v.x + v.y + v.z + v.w;
        }
        if (tid < (g & 3)) acc += sizes[(nfull << 2) + tid];
    }
    #pragma unroll
    for (int m = 16; m; m >>= 1) acc += __shfl_xor_sync(0xffffffffu, acc, m);
    if (lane == 0) wsum[wid] = acc;
    __syncthreads();
    if (tid == 0) {
        int o = 0;
        #pragma unroll
        for (int w = 0; w < NT / 32; w++) o += wsum[w];
        sh_off = o;
    }
    __syncthreads();
    const int offset = sh_off;
    const int size   = sizes[g];
    const int nw64   = (size + 63) >> 6;   // warps holding data (64 elems each)

    // Composite keys: (sortable(val) << 32) | ~elem_idx. Descending composite
    // order == descending value, ascending index on ties. Lane holds elements
    // i0 = wid*64+lane (key0) and i1 = wid*64+32+lane (key1).
    const int i0 = (wid << 6) + lane;
    const int i1 = i0 + 32;
    unsigned long long key0 = (unsigned long long)(unsigned int)(~(unsigned int)i0);
    unsigned long long key1 = (unsigned long long)(unsigned int)(~(unsigned int)i1);

    if (wid < nw64) {
        if (i0 < size) {
            float v = __ldg(&emb[(size_t)(offset + i0) * EMB_DIM + (EMB_DIM - 1)]);
            key0 |= (unsigned long long)float_to_sortable(v) << 32;
        }
        if (i1 < size) {
            float v = __ldg(&emb[(size_t)(offset + i1) * EMB_DIM + (EMB_DIM - 1)]);
            key1 |= (unsigned long long)float_to_sortable(v) << 32;
        }

        // ---- 64-element bitonic sort (descending), 2 keys per lane ----
        #pragma unroll
        for (int k = 2; k <= 16; k <<= 1) {
            const bool dir = ((lane & k) == 0);
            #pragma unroll
            for (int j = k >> 1; j >= 1; j >>= 1) {
                bool lower = (lane & j) == 0;
                key0 = cmpx(key0, shflx64(key0, j), lower == dir);
                key1 = cmpx(key1, shflx64(key1, j), lower == dir);
            }
        }
        // k = 32: key0 half descending, key1 half ascending.
        #pragma unroll
        for (int j = 16; j >= 1; j >>= 1) {
            bool lower = (lane & j) == 0;
            key0 = cmpx(key0, shflx64(key0, j), lower);
            key1 = cmpx(key1, shflx64(key1, j), !lower);
        }
        // k = 64: intra-thread compare keeps the top half, then 5-stage clean.
        {
            unsigned long long mx = key0 > key1 ? key0 : key1;
            key0 = warp_merge_desc(mx, lane);
        }
        s[(wid << 5) + lane] = key0;   // warp's top-32 of its 64, descending
    }
    __syncthreads();

    // ---- top-32 merge tree over nw64 sorted runs ----
    for (int step = 1; step < nw64; step <<= 1) {
        bool winner = ((wid & (2 * step - 1)) == 0) && (wid + step < nw64);
        if (winner) {
            unsigned long long other = s[((wid + step) << 5) + (31 - lane)];
            key0 = key0 > other ? key0 : other;
            key0 = warp_merge_desc(key0, lane);
            s[(wid << 5) + lane] = key0;
        }
        __syncthreads();
    }

    // ---- warp 0 lane r holds rank-r key: publish indices, then re-sort the
    //      winners by node index ASCENDING so the gather walks memory in
    //      address order (DRAM row locality). Stores scatter to rank slots.
    const int kmax = min(K_TOP, size);
    if (wid == 0) {
        int lidx = (int)(~(unsigned int)(key0 & 0xFFFFFFFFull));
        if (lane < K_TOP) {
            float idxval = (lane < kmax) ? (float)(offset + lidx) : -1.0f;
            out[(size_t)G * K_TOP * EMB_DIM + (size_t)g * K_TOP + lane] = idxval;
        }
        // pack (node_idx << 8) | rank; invalids ordered AFTER valids, and
        // lanes >= K_TOP forced to the very end so slots 0..29 carry ranks 0..29.
        unsigned pk;
        if (lane < kmax)            pk = ((unsigned)lidx << 8) | (unsigned)lane;
        else if (lane < K_TOP)      pk = 0x7FFF00u | (unsigned)lane;   // zero-row
        else                        pk = 0xFFFF0000u | (unsigned)lane; // discard
        // 32-element ascending bitonic sort (shuffles)
        #pragma unroll
        for (int k = 2; k <= 16; k <<= 1) {
            const bool dir = ((lane & k) != 0);   // ascending overall
            #pragma unroll
            for (int j = k >> 1; j >= 1; j >>= 1) {
                bool lower = (lane & j) == 0;
                unsigned other = __shfl_xor_sync(0xffffffffu, pk, j);
                pk = cmpx32(pk, other, lower == dir);
            }
        }
        #pragma unroll
        for (int j = 16; j >= 1; j >>= 1) {       // final ascending merge
            bool lower = (lane & j) == 0;
            unsigned other = __shfl_xor_sync(0xffffffffu, pk, j);
            pk = cmpx32(pk, other, !lower);
        }
        sidx[lane]  = (int)(pk >> 8);
        srank[lane] = (int)(pk & 0xFFu);
    }
    __syncthreads();

    // ---- gather 30 rows x 128 f32 in ascending node-address order ----
    // Warp w handles sorted slots {w, w+4, ..., w+28}; loads batched first.
    {
        float4*       out4 = (float4*)(out + (size_t)g * K_TOP * EMB_DIM);
        const float4* emb4 = (const float4*)emb;
        const float4  zero = make_float4(0.f, 0.f, 0.f, 0.f);

        float4 vals[8];
        int    rks[8];
        #pragma unroll
        for (int j = 0; j < 8; j++) {
            const int r  = wid + 4 * j;
            const bool ok = (r < K_TOP);
            const int a  = ok ? sidx[r] : 0;
            rks[j]       = ok ? srank[r] : 0;
            vals[j] = (ok && r < kmax)
                    ? __ldg(&emb4[(size_t)(offset + a) * 32 + lane])
                    : zero;
        }
        #pragma unroll
        for (int j = 0; j < 8; j++) {
            const int r = wid + 4 * j;
            if (r < K_TOP) out4[rks[j] * 32 + lane] = vals[j];
        }
    }
}

extern "C" void kernel_launch(void* const* d_in, const int* in_sizes, int n_in,
                              void* d_out, int out_size) {
    const float* emb   = (const float*)d_in[0];
    const int*   sizes = (const int*)d_in[1];
    const int G = in_sizes[1];
    sortpool_kernel<<<G, NT>>>(emb, sizes, (float*)d_out, G);
}

// round 10
// speedup vs baseline: 1.1277x; 1.0915x over previous
#include <cuda_runtime.h>
#include <cstdint>

#define K_TOP    30
#define EMB_DIM  128
#define NT       128   // 4 warps per block

// Map float -> uint32 whose unsigned order matches float order (ascending).
__device__ __forceinline__ unsigned int float_to_sortable(float f) {
    unsigned int b = __float_as_uint(f);
    return (b & 0x80000000u) ? ~b : (b | 0x80000000u);
}

__device__ __forceinline__ unsigned long long shflx64(unsigned long long x, int m) {
    unsigned lo = (unsigned)x, hi = (unsigned)(x >> 32);
    lo = __shfl_xor_sync(0xffffffffu, lo, m);
    hi = __shfl_xor_sync(0xffffffffu, hi, m);
    return ((unsigned long long)hi << 32) | lo;
}

__device__ __forceinline__ unsigned long long cmpx(unsigned long long a,
                                                   unsigned long long b,
                                                   bool keep_max) {
    unsigned long long mx = a > b ? a : b;
    unsigned long long mn = a > b ? b : a;
    return keep_max ? mx : mn;
}

// 5-stage descending bitonic merge (32-wide) of a bitonic sequence.
__device__ __forceinline__ unsigned long long warp_merge_desc(unsigned long long key,
                                                              int lane) {
    #pragma unroll
    for (int j = 16; j >= 1; j >>= 1) {
        bool lower = (lane & j) == 0;
        unsigned long long other = shflx64(key, j);
        key = cmpx(key, other, lower);
    }
    return key;
}

// Volatile vector load: ptxas may NOT reorder volatile memory ops relative to
// other memory ops, so a block of these issues back-to-back (true MLP) and the
// results stay live until consumed.
__device__ __forceinline__ float4 ldv4(const float4* p) {
    float4 v;
    asm volatile("ld.volatile.global.v4.f32 {%0,%1,%2,%3}, [%4];"
                 : "=f"(v.x), "=f"(v.y), "=f"(v.z), "=f"(v.w)
                 : "l"(p) : "memory");
    return v;
}

__global__ void __launch_bounds__(NT)
sortpool_kernel(const float* __restrict__ emb,
                const int*   __restrict__ sizes,
                float*       __restrict__ out,
                int G) {
    const int g    = blockIdx.x;
    const int tid  = threadIdx.x;
    const int lane = tid & 31;
    const int wid  = tid >> 5;

    __shared__ unsigned long long s[NT];      // one 32-slot run per warp
    __shared__ int wsum[NT / 32];
    __shared__ int sh_off;
    __shared__ int tops[32];

    // ---- offset = prefix sum of sizes[0..g-1], int4-vectorized (L2-resident) ----
    int acc = 0;
    {
        const int4* s4 = (const int4*)sizes;
        const int nfull = g >> 2;
        for (int j = tid; j < nfull; j += NT) {
            int4 v = s4[j];
            acc += v.x + v.y + v.z + v.w;
        }
        if (tid < (g & 3)) acc += sizes[(nfull << 2) + tid];
    }
    #pragma unroll
    for (int m = 16; m; m >>= 1) acc += __shfl_xor_sync(0xffffffffu, acc, m);
    if (lane == 0) wsum[wid] = acc;
    __syncthreads();
    if (tid == 0) {
        int o = 0;
        #pragma unroll
        for (int w = 0; w < NT / 32; w++) o += wsum[w];
        sh_off = o;
    }
    __syncthreads();
    const int offset = sh_off;
    const int size   = sizes[g];
    const int nw64   = (size + 63) >> 6;   // warps holding data (64 elems each)

    // Composite keys: (sortable(val) << 32) | ~elem_idx. Descending composite
    // order == descending value, ascending index on ties. Lane holds elements
    // i0 = wid*64+lane (key0) and i1 = wid*64+32+lane (key1).
    const int i0 = (wid << 6) + lane;
    const int i1 = i0 + 32;
    unsigned long long key0 = (unsigned long long)(unsigned int)(~(unsigned int)i0);
    unsigned long long key1 = (unsigned long long)(unsigned int)(~(unsigned int)i1);

    if (wid < nw64) {
        if (i0 < size) {
            float v = __ldg(&emb[(size_t)(offset + i0) * EMB_DIM + (EMB_DIM - 1)]);
            key0 |= (unsigned long long)float_to_sortable(v) << 32;
        }
        if (i1 < size) {
            float v = __ldg(&emb[(size_t)(offset + i1) * EMB_DIM + (EMB_DIM - 1)]);
            key1 |= (unsigned long long)float_to_sortable(v) << 32;
        }

        // ---- 64-element bitonic sort (descending), 2 keys per lane ----
        #pragma unroll
        for (int k = 2; k <= 16; k <<= 1) {
            const bool dir = ((lane & k) == 0);
            #pragma unroll
            for (int j = k >> 1; j >= 1; j >>= 1) {
                bool lower = (lane & j) == 0;
                key0 = cmpx(key0, shflx64(key0, j), lower == dir);
                key1 = cmpx(key1, shflx64(key1, j), lower == dir);
            }
        }
        // k = 32: key0 half descending, key1 half ascending.
        #pragma unroll
        for (int j = 16; j >= 1; j >>= 1) {
            bool lower = (lane & j) == 0;
            key0 = cmpx(key0, shflx64(key0, j), lower);
            key1 = cmpx(key1, shflx64(key1, j), !lower);
        }
        // k = 64: intra-thread compare keeps the top half, then 5-stage clean.
        {
            unsigned long long mx = key0 > key1 ? key0 : key1;
            key0 = warp_merge_desc(mx, lane);
        }
        s[(wid << 5) + lane] = key0;   // warp's top-32 of its 64, descending
    }
    __syncthreads();

    // ---- top-32 merge tree over nw64 sorted runs ----
    for (int step = 1; step < nw64; step <<= 1) {
        bool winner = ((wid & (2 * step - 1)) == 0) && (wid + step < nw64);
        if (winner) {
            unsigned long long other = s[((wid + step) << 5) + (31 - lane)];
            key0 = key0 > other ? key0 : other;
            key0 = warp_merge_desc(key0, lane);
            s[(wid << 5) + lane] = key0;
        }
        __syncthreads();
    }

    // ---- warp 0 lane r holds rank-r key; publish indices ----
    const int kmax = min(K_TOP, size);
    if (wid == 0) {
        int lidx = (int)(~(unsigned int)(key0 & 0xFFFFFFFFull));
        tops[lane] = lidx;
        if (lane < K_TOP) {
            float idxval = (lane < kmax) ? (float)(offset + lidx) : -1.0f;
            out[(size_t)G * K_TOP * EMB_DIM + (size_t)g * K_TOP + lane] = idxval;
        }
    }
    __syncthreads();

    // ---- gather 30 rows x 128 f32: warp w owns rows {w, w+4, ..., w+28} ----
    // All 8 row loads are VOLATILE vector loads issued back-to-back: ptxas is
    // forbidden from sinking them into the store sequence -> guaranteed MLP=8.
    // Invalid slots (r >= kmax) load a safe dummy row and are masked at store.
    {
        float4*       out4 = (float4*)(out + (size_t)g * K_TOP * EMB_DIM);
        const float4* emb4 = (const float4*)emb;
        const float4  zero = make_float4(0.f, 0.f, 0.f, 0.f);

        int addr[8];
        #pragma unroll
        for (int j = 0; j < 8; j++) {
            const int r = wid + 4 * j;
            addr[j] = (r < kmax) ? tops[r] : tops[0];   // dummy = rank-0 row
        }

        float4 v[8];
        #pragma unroll
        for (int j = 0; j < 8; j++)
            v[j] = ldv4(&emb4[(size_t)(offset + addr[j]) * 32 + lane]);

        #pragma unroll
        for (int j = 0; j < 8; j++) {
            const int r = wid + 4 * j;
            if (r < K_TOP)
                out4[r * 32 + lane] = (r < kmax) ? v[j] : zero;
        }
    }
}

extern "C" void kernel_launch(void* const* d_in, const int* in_sizes, int n_in,
                              void* d_out, int out_size) {
    const float* emb   = (const float*)d_in[0];
    const int*   sizes = (const int*)d_in[1];
    const int G = in_sizes[1];
    sortpool_kernel<<<G, NT>>>(emb, sizes, (float*)d_out, G);
}

// round 11
// speedup vs baseline: 1.1804x; 1.0468x over previous
#include <cuda_runtime.h>
#include <cstdint>

#define K_TOP    30
#define EMB_DIM  128
#define NT       128   // 4 warps per block; each block handles TWO graphs

// Map float -> uint32 whose unsigned order matches float order (ascending).
__device__ __forceinline__ unsigned int float_to_sortable(float f) {
    unsigned int b = __float_as_uint(f);
    return (b & 0x80000000u) ? ~b : (b | 0x80000000u);
}

__device__ __forceinline__ unsigned long long shflx64(unsigned long long x, int m) {
    unsigned lo = (unsigned)x, hi = (unsigned)(x >> 32);
    lo = __shfl_xor_sync(0xffffffffu, lo, m);
    hi = __shfl_xor_sync(0xffffffffu, hi, m);
    return ((unsigned long long)hi << 32) | lo;
}

__device__ __forceinline__ unsigned long long cmpx(unsigned long long a,
                                                   unsigned long long b,
                                                   bool keep_max) {
    unsigned long long mx = a > b ? a : b;
    unsigned long long mn = a > b ? b : a;
    return keep_max ? mx : mn;
}

// 5-stage descending bitonic merge (32-wide) of a bitonic sequence.
__device__ __forceinline__ unsigned long long warp_merge_desc(unsigned long long key,
                                                              int lane) {
    #pragma unroll
    for (int j = 16; j >= 1; j >>= 1) {
        bool lower = (lane & j) == 0;
        unsigned long long other = shflx64(key, j);
        key = cmpx(key, other, lower);
    }
    return key;
}

// Volatile vector load: ptxas may not sink these into the store sequence, so a
// block of them issues back-to-back (true MLP) with results held in registers.
__device__ __forceinline__ float4 ldv4(const float4* p) {
    float4 v;
    asm volatile("ld.volatile.global.v4.f32 {%0,%1,%2,%3}, [%4];"
                 : "=f"(v.x), "=f"(v.y), "=f"(v.z), "=f"(v.w)
                 : "l"(p) : "memory");
    return v;
}

// 64-element descending bitonic sort, 2 keys per lane; returns warp top-32.
__device__ __forceinline__ unsigned long long warp_sort64_top32(
        unsigned long long key0, unsigned long long key1, int lane) {
    #pragma unroll
    for (int k = 2; k <= 16; k <<= 1) {
        const bool dir = ((lane & k) == 0);
        #pragma unroll
        for (int j = k >> 1; j >= 1; j >>= 1) {
            bool lower = (lane & j) == 0;
            key0 = cmpx(key0, shflx64(key0, j), lower == dir);
            key1 = cmpx(key1, shflx64(key1, j), lower == dir);
        }
    }
    // k = 32: key0 half descending, key1 half ascending.
    #pragma unroll
    for (int j = 16; j >= 1; j >>= 1) {
        bool lower = (lane & j) == 0;
        key0 = cmpx(key0, shflx64(key0, j), lower);
        key1 = cmpx(key1, shflx64(key1, j), !lower);
    }
    // k = 64: intra-thread compare keeps the top half, then 5-stage clean.
    unsigned long long mx = key0 > key1 ? key0 : key1;
    return warp_merge_desc(mx, lane);
}

__global__ void __launch_bounds__(NT)
sortpool_kernel(const float* __restrict__ emb,
                const int*   __restrict__ sizes,
                float*       __restrict__ out,
                int G) {
    const int gA   = 2 * blockIdx.x;
    const int gB   = gA + 1;
    const bool hasB = (gB < G);
    const int tid  = threadIdx.x;
    const int lane = tid & 31;
    const int wid  = tid >> 5;

    __shared__ unsigned long long s[NT];      // one 32-slot run per warp
    __shared__ int wsum[NT / 32];
    __shared__ int sh_off;
    __shared__ int topsA[32];
    __shared__ int topsB[32];

    // ---- offset of gA = prefix sum of sizes[0..gA-1] (done ONCE per CTA) ----
    int acc = 0;
    {
        const int4* s4 = (const int4*)sizes;
        const int nfull = gA >> 2;
        for (int j = tid; j < nfull; j += NT) {
            int4 v = s4[j];
            acc += v.x + v.y + v.z + v.w;
        }
        if (tid < (gA & 3)) acc += sizes[(nfull << 2) + tid];
    }
    #pragma unroll
    for (int m = 16; m; m >>= 1) acc += __shfl_xor_sync(0xffffffffu, acc, m);
    if (lane == 0) wsum[wid] = acc;
    __syncthreads();
    if (tid == 0) {
        int o = 0;
        #pragma unroll
        for (int w = 0; w < NT / 32; w++) o += wsum[w];
        sh_off = o;
    }
    __syncthreads();
    const int offA  = sh_off;
    const int sizeA = sizes[gA];
    const int offB  = offA + sizeA;
    const int sizeB = hasB ? sizes[gB] : 0;
    const int nwA   = (sizeA + 63) >> 6;
    const int nwB   = (sizeB + 63) >> 6;

    // ---- load keys for BOTH graphs up front (B's latency hides under phase A) ----
    // Composite key: (sortable(val) << 32) | ~elem_idx. Descending composite
    // order == descending value, ascending index on ties.
    const int i0 = (wid << 6) + lane;
    const int i1 = i0 + 32;
    unsigned long long a0 = (unsigned long long)(unsigned int)(~(unsigned int)i0);
    unsigned long long a1 = (unsigned long long)(unsigned int)(~(unsigned int)i1);
    unsigned long long b0 = a0, b1 = a1;

    if (wid < nwA && i0 < sizeA)
        a0 |= (unsigned long long)float_to_sortable(
                __ldg(&emb[(size_t)(offA + i0) * EMB_DIM + (EMB_DIM - 1)])) << 32;
    if (wid < nwA && i1 < sizeA)
        a1 |= (unsigned long long)float_to_sortable(
                __ldg(&emb[(size_t)(offA + i1) * EMB_DIM + (EMB_DIM - 1)])) << 32;
    if (wid < nwB && i0 < sizeB)
        b0 |= (unsigned long long)float_to_sortable(
                __ldg(&emb[(size_t)(offB + i0) * EMB_DIM + (EMB_DIM - 1)])) << 32;
    if (wid < nwB && i1 < sizeB)
        b1 |= (unsigned long long)float_to_sortable(
                __ldg(&emb[(size_t)(offB + i1) * EMB_DIM + (EMB_DIM - 1)])) << 32;

    // ================= PHASE A : sort + merge + gather graph gA =================
    unsigned long long keyA = 0;
    if (wid < nwA) {
        keyA = warp_sort64_top32(a0, a1, lane);
        s[(wid << 5) + lane] = keyA;
    }
    __syncthreads();
    for (int step = 1; step < nwA; step <<= 1) {
        bool winner = ((wid & (2 * step - 1)) == 0) && (wid + step < nwA);
        if (winner) {
            unsigned long long other = s[((wid + step) << 5) + (31 - lane)];
            keyA = keyA > other ? keyA : other;
            keyA = warp_merge_desc(keyA, lane);
            s[(wid << 5) + lane] = keyA;
        }
        __syncthreads();
    }
    const int kmaxA = min(K_TOP, sizeA);
    if (wid == 0) {
        int lidx = (int)(~(unsigned int)(keyA & 0xFFFFFFFFull));
        topsA[lane] = lidx;
        if (lane < K_TOP) {
            float idxval = (lane < kmaxA) ? (float)(offA + lidx) : -1.0f;
            out[(size_t)G * K_TOP * EMB_DIM + (size_t)gA * K_TOP + lane] = idxval;
        }
    }
    __syncthreads();

    {   // gather A: warp w owns rows {w, w+4, ..., w+28}, volatile MLP-8
        float4*       out4 = (float4*)(out + (size_t)gA * K_TOP * EMB_DIM);
        const float4* emb4 = (const float4*)emb;
        const float4  zero = make_float4(0.f, 0.f, 0.f, 0.f);

        int addr[8];
        #pragma unroll
        for (int j = 0; j < 8; j++) {
            const int r = wid + 4 * j;
            addr[j] = (r < kmaxA) ? topsA[r] : topsA[0];
        }
        float4 v[8];
        #pragma unroll
        for (int j = 0; j < 8; j++)
            v[j] = ldv4(&emb4[(size_t)(offA + addr[j]) * 32 + lane]);
        #pragma unroll
        for (int j = 0; j < 8; j++) {
            const int r = wid + 4 * j;
            if (r < K_TOP) out4[r * 32 + lane] = (r < kmaxA) ? v[j] : zero;
        }
    }

    // ================= PHASE B : sort overlaps A's store drain =================
    unsigned long long keyB = 0;
    if (wid < nwB) {
        keyB = warp_sort64_top32(b0, b1, lane);
        s[(wid << 5) + lane] = keyB;
    }
    __syncthreads();
    for (int step = 1; step < nwB; step <<= 1) {
        bool winner = ((wid & (2 * step - 1)) == 0) && (wid + step < nwB);
        if (winner) {
            unsigned long long other = s[((wid + step) << 5) + (31 - lane)];
            keyB = keyB > other ? keyB : other;
            keyB = warp_merge_desc(keyB, lane);
            s[(wid << 5) + lane] = keyB;
        }
        __syncthreads();
    }
    const int kmaxB = min(K_TOP, sizeB);
    if (hasB && wid == 0) {
        int lidx = (int)(~(unsigned int)(keyB & 0xFFFFFFFFull));
        topsB[lane] = lidx;
        if (lane < K_TOP) {
            float idxval = (lane < kmaxB) ? (float)(offB + lidx) : -1.0f;
            out[(size_t)G * K_TOP * EMB_DIM + (size_t)gB * K_TOP + lane] = idxval;
        }
    }
    __syncthreads();

    if (hasB) {   // gather B
        float4*       out4 = (float4*)(out + (size_t)gB * K_TOP * EMB_DIM);
        const float4* emb4 = (const float4*)emb;
        const float4  zero = make_float4(0.f, 0.f, 0.f, 0.f);

        int addr[8];
        #pragma unroll
        for (int j = 0; j < 8; j++) {
            const int r = wid + 4 * j;
            addr[j] = (r < kmaxB) ? topsB[r] : topsB[0];
        }
        float4 v[8];
        #pragma unroll
        for (int j = 0; j < 8; j++)
            v[j] = ldv4(&emb4[(size_t)(offB + addr[j]) * 32 + lane]);
        #pragma unroll
        for (int j = 0; j < 8; j++) {
            const int r = wid + 4 * j;
            if (r < K_TOP) out4[r * 32 + lane] = (r < kmaxB) ? v[j] : zero;
        }
    }
}

extern "C" void kernel_launch(void* const* d_in, const int* in_sizes, int n_in,
                              void* d_out, int out_size) {
    const float* emb   = (const float*)d_in[0];
    const int*   sizes = (const int*)d_in[1];
    const int G = in_sizes[1];
    const int blocks = (G + 1) / 2;
    sortpool_kernel<<<blocks, NT>>>(emb, sizes, (float*)d_out, G);
}